// round 3
// baseline (speedup 1.0000x reference)
#include <cuda_runtime.h>

#define T_STEPS 128
#define IN_DIM  32
#define HID     64
#define G4      256           // 4*HID gate columns
#define KDIM    96            // IN_DIM + HID
#define TB      64            // batches per block
#define DROW    136           // duplicated D row stride (floats): 128 data + 8 pad
#define DBUF    (KDIM * DROW)
#define NT      256
#define BATCH   8192

// scratch: x transposed to [T][IN][B] for coalesced per-step tile loads
__device__ float g_xT[(size_t)T_STEPS * IN_DIM * BATCH];

__global__ void transpose_x_kernel(const float* __restrict__ x) {
    __shared__ float tile[32][33];
    const int t  = blockIdx.y;
    const int b0 = blockIdx.x * 32;
    const int c  = threadIdx.x & 31;
    const int r0 = threadIdx.x >> 5;
#pragma unroll
    for (int r = 0; r < 4; ++r) {
        int row = r0 + r * 8;
        tile[row][c] = x[((size_t)(b0 + row) * T_STEPS + t) * IN_DIM + c];
    }
    __syncthreads();
#pragma unroll
    for (int r = 0; r < 4; ++r) {
        int kk = r0 + r * 8;
        g_xT[((size_t)t * IN_DIM + kk) * BATCH + b0 + c] = tile[c][kk];
    }
}

__device__ __forceinline__ float tanh_a(float x) {
    float y;
    asm("tanh.approx.f32 %0, %1;" : "=f"(y) : "f"(x));
    return y;
}
__device__ __forceinline__ float sig_a(float x) {
    return 0.5f + 0.5f * tanh_a(0.5f * x);
}
__device__ __forceinline__ unsigned long long pack2(float a, float b) {
    unsigned long long r;
    asm("mov.b64 %0, {%1, %2};" : "=l"(r)
        : "r"(__float_as_uint(a)), "r"(__float_as_uint(b)));
    return r;
}
__device__ __forceinline__ void unpack2(unsigned long long v, float& a, float& b) {
    unsigned int lo, hi;
    asm("mov.b64 {%0, %1}, %2;" : "=r"(lo), "=r"(hi) : "l"(v));
    a = __uint_as_float(lo);
    b = __uint_as_float(hi);
}
#define FMA2(acc, a, b) \
    asm("fma.rn.f32x2 %0, %1, %2, %0;" : "+l"(acc) : "l"(a), "l"(b))

__global__ __launch_bounds__(NT)
void lstm_kernel(const float* __restrict__ W_ih, const float* __restrict__ W_hh,
                 const float* __restrict__ b_ih, const float* __restrict__ b_hh,
                 const float* __restrict__ W_fc, const float* __restrict__ b_fc,
                 float* __restrict__ out)
{
    extern __shared__ float smem[];
    float* Wt = smem;                    // [KDIM][G4] weights, gate-interleaved
    float* D0 = smem + KDIM * G4;        // duplicated rows: [KDIM][DROW], val at 2*b, 2*b+1
    float* D1 = D0 + DBUF;               // rows 0..31: x_t (dup) ; rows 32..95: h (dup)

    const int tid = threadIdx.x;
    const int ty  = tid >> 3;            // 0..31 -> hidden units 2ty, 2ty+1 (8 gate cols)
    const int tx  = tid & 7;             // batch group: batches 4tx..4tx+3 and 32+4tx..+3
    const int b0  = blockIdx.x * TB;

    // ---- one-time: load & reorder weights: Wt[k][4*h+q], q in (i,f,g,o) ----
    for (int idx = tid; idx < KDIM * G4; idx += NT) {
        int k   = idx >> 8;
        int col = idx & 255;
        int h   = col >> 2;
        int q   = col & 3;
        float v = (k < IN_DIM) ? W_ih[(q * HID + h) * IN_DIM + k]
                               : W_hh[(q * HID + h) * HID + (k - IN_DIM)];
        Wt[idx] = v;
    }
    // zero h region of buffer 0 (read at t=0); 64 rows x 128 floats
    for (int idx = tid; idx < HID * 128; idx += NT) {
        D0[(IN_DIM + (idx >> 7)) * DROW + (idx & 127)] = 0.0f;
    }

    // bias pairs: [0]=(i,f) h0, [1]=(g,o) h0, [2]=(i,f) h1, [3]=(g,o) h1
    const int h0 = 2 * ty, h1 = 2 * ty + 1;
    unsigned long long bias2[4];
    {
        float bi0 = b_ih[0 * HID + h0] + b_hh[0 * HID + h0];
        float bf0 = b_ih[1 * HID + h0] + b_hh[1 * HID + h0];
        float bg0 = b_ih[2 * HID + h0] + b_hh[2 * HID + h0];
        float bo0 = b_ih[3 * HID + h0] + b_hh[3 * HID + h0];
        float bi1 = b_ih[0 * HID + h1] + b_hh[0 * HID + h1];
        float bf1 = b_ih[1 * HID + h1] + b_hh[1 * HID + h1];
        float bg1 = b_ih[2 * HID + h1] + b_hh[2 * HID + h1];
        float bo1 = b_ih[3 * HID + h1] + b_hh[3 * HID + h1];
        bias2[0] = pack2(bi0, bf0);
        bias2[1] = pack2(bg0, bo0);
        bias2[2] = pack2(bi1, bf1);
        bias2[3] = pack2(bg1, bo1);
    }

    // x staging: thread owns (row kk, 8 batches starting at 8*li)
    const int kk = tid >> 3;             // 0..31
    const int li = tid & 7;              // 0..7
    const float* xsrc = &g_xT[(size_t)kk * BATCH + b0 + 8 * li];
    float4 xa = *(const float4*)(xsrc);
    float4 xb = *(const float4*)(xsrc + 4);

    __syncthreads();                     // weights + zeroed h visible
    {   // stage x_0 duplicated into D0
        float* drow = &D0[kk * DROW + 16 * li];
        ((float4*)drow)[0] = make_float4(xa.x, xa.x, xa.y, xa.y);
        ((float4*)drow)[1] = make_float4(xa.z, xa.z, xa.w, xa.w);
        ((float4*)drow)[2] = make_float4(xb.x, xb.x, xb.y, xb.y);
        ((float4*)drow)[3] = make_float4(xb.z, xb.z, xb.w, xb.w);
    }
    xa = *(const float4*)(xsrc + (size_t)IN_DIM * BATCH);
    xb = *(const float4*)(xsrc + (size_t)IN_DIM * BATCH + 4);
    __syncthreads();

    float c0[8], c1[8];
#pragma unroll
    for (int j = 0; j < 8; ++j) { c0[j] = 0.0f; c1[j] = 0.0f; }

    const float* wp = Wt + 8 * ty;

    for (int t = 0; t < T_STEPS; ++t) {
        const float* cur = (t & 1) ? D1 : D0;
        float*       nxt = (t & 1) ? D0 : D1;
        const float* dp  = cur + 8 * tx;

        unsigned long long acc[4][8];    // [pair][batch]
#pragma unroll
        for (int p = 0; p < 4; ++p)
#pragma unroll
            for (int j = 0; j < 8; ++j) acc[p][j] = bias2[p];

#pragma unroll 8
        for (int k = 0; k < KDIM; ++k) {
            // weights: 8 consecutive cols = 4 natural f32x2 pairs, no packing
            ulonglong2 wA = *(const ulonglong2*)(wp + k * G4);       // (i,f),(g,o) of h0
            ulonglong2 wB = *(const ulonglong2*)(wp + k * G4 + 4);   // (i,f),(g,o) of h1
            // data: duplicated (d,d) pairs straight from LDS
            ulonglong2 dA0 = *(const ulonglong2*)(dp + k * DROW);        // batches 4tx,4tx+1
            ulonglong2 dA1 = *(const ulonglong2*)(dp + k * DROW + 4);    // 4tx+2,4tx+3
            ulonglong2 dB0 = *(const ulonglong2*)(dp + k * DROW + 64);   // 32+4tx,..
            ulonglong2 dB1 = *(const ulonglong2*)(dp + k * DROW + 68);
            unsigned long long dd[8] = {dA0.x, dA0.y, dA1.x, dA1.y,
                                        dB0.x, dB0.y, dB1.x, dB1.y};
#pragma unroll
            for (int j = 0; j < 8; ++j) {
                FMA2(acc[0][j], wA.x, dd[j]);
                FMA2(acc[1][j], wA.y, dd[j]);
                FMA2(acc[2][j], wB.x, dd[j]);
                FMA2(acc[3][j], wB.y, dd[j]);
            }
        }

        // elementwise update (register-resident c), h for 2 hidden units x 8 batches
        float h0v[8], h1v[8];
#pragma unroll
        for (int j = 0; j < 8; ++j) {
            float iv, fv, gv, ov;
            unpack2(acc[0][j], iv, fv);
            unpack2(acc[1][j], gv, ov);
            float cn = sig_a(fv) * c0[j] + sig_a(iv) * tanh_a(gv);
            c0[j] = cn;
            h0v[j] = sig_a(ov) * tanh_a(cn);
            unpack2(acc[2][j], iv, fv);
            unpack2(acc[3][j], gv, ov);
            cn = sig_a(fv) * c1[j] + sig_a(iv) * tanh_a(gv);
            c1[j] = cn;
            h1v[j] = sig_a(ov) * tanh_a(cn);
        }

        // write h (duplicated) into the other buffer
        {
            float* r0 = &nxt[(IN_DIM + h0) * DROW + 8 * tx];
            float* r1 = &nxt[(IN_DIM + h1) * DROW + 8 * tx];
            ((float4*)r0)[0]  = make_float4(h0v[0], h0v[0], h0v[1], h0v[1]);
            ((float4*)r0)[1]  = make_float4(h0v[2], h0v[2], h0v[3], h0v[3]);
            ((float4*)(r0 + 64))[0] = make_float4(h0v[4], h0v[4], h0v[5], h0v[5]);
            ((float4*)(r0 + 64))[1] = make_float4(h0v[6], h0v[6], h0v[7], h0v[7]);
            ((float4*)r1)[0]  = make_float4(h1v[0], h1v[0], h1v[1], h1v[1]);
            ((float4*)r1)[1]  = make_float4(h1v[2], h1v[2], h1v[3], h1v[3]);
            ((float4*)(r1 + 64))[0] = make_float4(h1v[4], h1v[4], h1v[5], h1v[5]);
            ((float4*)(r1 + 64))[1] = make_float4(h1v[6], h1v[6], h1v[7], h1v[7]);
        }
        if (t + 1 < T_STEPS) {
            // stage x_{t+1} duplicated
            float* drow = &nxt[kk * DROW + 16 * li];
            ((float4*)drow)[0] = make_float4(xa.x, xa.x, xa.y, xa.y);
            ((float4*)drow)[1] = make_float4(xa.z, xa.z, xa.w, xa.w);
            ((float4*)drow)[2] = make_float4(xb.x, xb.x, xb.y, xb.y);
            ((float4*)drow)[3] = make_float4(xb.z, xb.z, xb.w, xb.w);
            if (t + 2 < T_STEPS) {
                const float* p = xsrc + (size_t)(t + 2) * IN_DIM * BATCH;
                xa = *(const float4*)(p);
                xb = *(const float4*)(p + 4);
            }
        }
        __syncthreads();                  // single barrier per step
    }

    // final h lives in D0 (written when t=127, odd -> nxt=D0)
    // ---- final FC: out[b][o] = b_fc[o] + sum_h W_fc[o][h] * h_T[b][h] ----
    for (int idx = tid; idx < TB * 8; idx += NT) {
        int ob = idx >> 3;               // batch 0..63
        int oo = idx & 7;                // output 0..7
        float s = b_fc[oo];
#pragma unroll 8
        for (int h2 = 0; h2 < HID; ++h2)
            s += W_fc[oo * HID + h2] * D0[(IN_DIM + h2) * DROW + 2 * ob];
        out[(size_t)(b0 + ob) * 8 + oo] = s;
    }
}

extern "C" void kernel_launch(void* const* d_in, const int* in_sizes, int n_in,
                              void* d_out, int out_size)
{
    const float* x    = (const float*)d_in[0];
    const float* W_ih = (const float*)d_in[1];
    const float* W_hh = (const float*)d_in[2];
    const float* b_ih = (const float*)d_in[3];
    const float* b_hh = (const float*)d_in[4];
    const float* W_fc = (const float*)d_in[5];
    const float* b_fc = (const float*)d_in[6];
    float* out = (float*)d_out;

    dim3 tg(BATCH / 32, T_STEPS);
    transpose_x_kernel<<<tg, 256>>>(x);

    size_t smem = (size_t)(KDIM * G4 + 2 * DBUF) * sizeof(float);
    cudaFuncSetAttribute(lstm_kernel, cudaFuncAttributeMaxDynamicSharedMemorySize, (int)smem);
    lstm_kernel<<<BATCH / TB, NT, smem>>>(W_ih, W_hh, b_ih, b_hh, W_fc, b_fc, out);
}

// round 5
// speedup vs baseline: 2.9552x; 2.9552x over previous
#include <cuda_runtime.h>
#include <cstdint>

#define NT       512
#define TB       64
#define BATCH    8192
#define T_STEPS  128
#define SA       100            // A row stride (floats)
#define SB       100            // B row stride (floats)
#define SG       260            // G row stride (floats)

#define A_FLTS   (256 * SA)     // 25600
#define B0_OFF   A_FLTS
#define B_FLTS   (64 * SB)      // 6400
#define B1_OFF   (B0_OFF + B_FLTS)
#define G_OFF    (B1_OFF + B_FLTS)
#define G_FLTS   (64 * SG)
#define SMEM_FLTS (G_OFF + G_FLTS)   // 55040 floats = 220160 B

static __device__ __forceinline__ float rtf32(float v) {   // round-to-nearest tf32
    unsigned u;
    asm("cvt.rna.tf32.f32 %0, %1;" : "=r"(u) : "f"(v));
    return __uint_as_float(u);
}
static __device__ __forceinline__ float tanh_a(float x) {
    float y;
    asm("tanh.approx.f32 %0, %1;" : "=f"(y) : "f"(x));
    return y;
}
static __device__ __forceinline__ void mma_tf32(
    float& d0, float& d1, float& d2, float& d3,
    unsigned a0, unsigned a1, unsigned a2, unsigned a3,
    unsigned b0, unsigned b1)
{
    asm volatile(
        "mma.sync.aligned.m16n8k8.row.col.f32.tf32.tf32.f32 "
        "{%0,%1,%2,%3}, {%4,%5,%6,%7}, {%8,%9}, {%0,%1,%2,%3};"
        : "+f"(d0), "+f"(d1), "+f"(d2), "+f"(d3)
        : "r"(a0), "r"(a1), "r"(a2), "r"(a3), "r"(b0), "r"(b1));
}
static __device__ __forceinline__ unsigned fb(float v) { return __float_as_uint(v); }

// k-permutation within an 8-wide k-tile: position p = (m&3)*2 + (m>>2)
// => (k, k+4) land at adjacent positions (2t, 2t+1): one LDS.64 per fragment.
static __device__ __forceinline__ int kperm(int k) {
    return (k & ~7) + ((k & 3) << 1) + ((k >> 2) & 1);
}

__global__ __launch_bounds__(NT, 1)
void lstm_kernel(const float* __restrict__ x,
                 const float* __restrict__ W_ih, const float* __restrict__ W_hh,
                 const float* __restrict__ b_ih, const float* __restrict__ b_hh,
                 const float* __restrict__ W_fc, const float* __restrict__ b_fc,
                 float* __restrict__ out)
{
    extern __shared__ float sm[];
    float* A  = sm;                       // [256 gate rows][SA] k-permuted, tf32-rounded
    float* B0 = sm + B0_OFF;              // [64 batch][SB]  k-permuted: x(0..31)|h(32..95)
    float* B1 = sm + B1_OFF;
    float* G  = sm + G_OFF;               // [64 batch][SG] activated gates, gate-major cols

    const int tid  = threadIdx.x;
    const int lane = tid & 31;
    const int w    = tid >> 5;            // 16 warps
    const int wm   = w & 7;               // M-tile index (32 rows each)
    const int wn   = w >> 3;              // N-tile index (32 cols each)
    const int g    = lane >> 2;           // group 0..7
    const int tq   = lane & 3;            // thread-in-group
    const int b0   = blockIdx.x * TB;
    const int q    = wm >> 1;             // gate type of this warp (0=i,1=f,2=g,3=o)

    // ---- one-time: A fill (gate-major rows, k-permuted, tf32-rounded) ----
    for (int idx = tid; idx < 256 * 96; idx += NT) {
        int r = idx / 96, k = idx - r * 96;
        float v = (k < 32) ? W_ih[r * 32 + k] : W_hh[r * 64 + (k - 32)];
        A[r * SA + kperm(k)] = rtf32(v);
    }
    // zero B0 (h region must be 0 at t=0)
    for (int idx = tid; idx < B_FLTS; idx += NT) B0[idx] = 0.0f;

    // per-warp activation biases (pre-halved for sigmoid gates)
    float bact[4];
#pragma unroll
    for (int i = 0; i < 4; ++i) {
        int grow = wm * 32 + i * 8 + g;
        float bv = b_ih[grow] + b_hh[grow];
        bact[i] = (q == 2) ? bv : 0.5f * bv;
    }

    // combine-thread constants: (batch cb, hidden group hg -> h = 8*hg..8*hg+7)
    const int cb = tid >> 3;
    const int hg = tid & 7;
    float c[8];
#pragma unroll
    for (int j = 0; j < 8; ++j) c[j] = 0.0f;
    float hlast[8];

    // x staging: thread owns (batch cb, 4 input dims 4*hg..4*hg+3)
    const float* xrow = x + ((size_t)(b0 + cb) * T_STEPS) * 32 + hg * 4;
    const int xbase = cb * SB + ((hg >> 1) << 3) + (hg & 1);   // k' of k=4*hg
    {
        float4 xv = *(const float4*)xrow;                      // x_0
        B0[xbase + 0] = rtf32(xv.x);
        B0[xbase + 2] = rtf32(xv.y);
        B0[xbase + 4] = rtf32(xv.z);
        B0[xbase + 6] = rtf32(xv.w);
    }
    float4 xpref = *(const float4*)(xrow + 32);                // x_1
    __syncthreads();

    const int rowa = wm * 32 + g;

    for (int t = 0; t < T_STEPS; ++t) {
        const float* Bc = (t & 1) ? B1 : B0;
        float*       Bn = (t & 1) ? B0 : B1;

        // ---- GEMM: warp tile 32(M) x 32(N), K=96 via 12 k-tiles ----
        float d[2][4][4];
#pragma unroll
        for (int mt = 0; mt < 2; ++mt)
#pragma unroll
            for (int nt = 0; nt < 4; ++nt)
#pragma unroll
                for (int r = 0; r < 4; ++r) d[mt][nt][r] = 0.0f;

#pragma unroll
        for (int kt = 0; kt < 12; ++kt) {
            unsigned a[2][4], bb[4][2];
#pragma unroll
            for (int mt = 0; mt < 2; ++mt) {
                float2 lo = *(const float2*)&A[(rowa + mt * 16) * SA + kt * 8 + 2 * tq];
                float2 hi = *(const float2*)&A[(rowa + mt * 16 + 8) * SA + kt * 8 + 2 * tq];
                a[mt][0] = fb(lo.x); a[mt][1] = fb(hi.x);
                a[mt][2] = fb(lo.y); a[mt][3] = fb(hi.y);
            }
#pragma unroll
            for (int nt = 0; nt < 4; ++nt) {
                float2 bv = *(const float2*)&Bc[(wn * 32 + nt * 8 + g) * SB + kt * 8 + 2 * tq];
                bb[nt][0] = fb(bv.x); bb[nt][1] = fb(bv.y);
            }
#pragma unroll
            for (int mt = 0; mt < 2; ++mt)
#pragma unroll
                for (int nt = 0; nt < 4; ++nt)
                    mma_tf32(d[mt][nt][0], d[mt][nt][1], d[mt][nt][2], d[mt][nt][3],
                             a[mt][0], a[mt][1], a[mt][2], a[mt][3],
                             bb[nt][0], bb[nt][1]);
        }

        // ---- activation + stage to G[batch][gate-row] ----
#pragma unroll
        for (int mt = 0; mt < 2; ++mt)
#pragma unroll
            for (int s = 0; s < 2; ++s) {
                const int grow = wm * 32 + mt * 16 + s * 8 + g;
                const float bv = bact[mt * 2 + s];
#pragma unroll
                for (int nt = 0; nt < 4; ++nt) {
                    int n0 = wn * 32 + nt * 8 + 2 * tq;
                    float v0 = d[mt][nt][2 * s + 0];
                    float v1 = d[mt][nt][2 * s + 1];
                    float r0, r1;
                    if (q == 2) {                 // g gate: tanh
                        r0 = tanh_a(v0 + bv);
                        r1 = tanh_a(v1 + bv);
                    } else {                      // i,f,o: sigmoid
                        r0 = 0.5f + 0.5f * tanh_a(0.5f * v0 + bv);
                        r1 = 0.5f + 0.5f * tanh_a(0.5f * v1 + bv);
                    }
                    G[n0 * SG + grow]       = r0;
                    G[(n0 + 1) * SG + grow] = r1;
                }
            }
        __syncthreads();

        // ---- combine: c/h update for (cb, h = 8*hg..+7) ----
        {
            const float* gr = &G[cb * SG + hg * 8];
            float4 i0 = ((const float4*)(gr +   0))[0], i1 = ((const float4*)(gr +   0))[1];
            float4 f0 = ((const float4*)(gr +  64))[0], f1 = ((const float4*)(gr +  64))[1];
            float4 g0 = ((const float4*)(gr + 128))[0], g1 = ((const float4*)(gr + 128))[1];
            float4 o0 = ((const float4*)(gr + 192))[0], o1 = ((const float4*)(gr + 192))[1];
            float iv[8] = {i0.x, i0.y, i0.z, i0.w, i1.x, i1.y, i1.z, i1.w};
            float fv[8] = {f0.x, f0.y, f0.z, f0.w, f1.x, f1.y, f1.z, f1.w};
            float gv[8] = {g0.x, g0.y, g0.z, g0.w, g1.x, g1.y, g1.z, g1.w};
            float ov[8] = {o0.x, o0.y, o0.z, o0.w, o1.x, o1.y, o1.z, o1.w};
            float hv[8];
#pragma unroll
            for (int j = 0; j < 8; ++j) {
                float cn = fv[j] * c[j] + iv[j] * gv[j];
                c[j] = cn;
                hv[j] = ov[j] * tanh_a(cn);
            }
            if (t + 1 < T_STEPS) {
                // h -> Bn (k = 32+8*hg+j; pairs (j, j+4) adjacent after kperm)
                const int hb = cb * SB + (4 + hg) * 8;
#pragma unroll
                for (int j = 0; j < 4; ++j)
                    *(float2*)&Bn[hb + 2 * j] =
                        make_float2(rtf32(hv[j]), rtf32(hv[j + 4]));
                // x_{t+1} -> Bn
                Bn[xbase + 0] = rtf32(xpref.x);
                Bn[xbase + 2] = rtf32(xpref.y);
                Bn[xbase + 4] = rtf32(xpref.z);
                Bn[xbase + 6] = rtf32(xpref.w);
                if (t + 2 < T_STEPS)
                    xpref = *(const float4*)(xrow + (size_t)(t + 2) * 32);
            } else {
#pragma unroll
                for (int j = 0; j < 8; ++j) hlast[j] = hv[j];
            }
        }
        __syncthreads();
    }

    // ---- stage h_T into G[batch][0..63], then FC ----
#pragma unroll
    for (int j = 0; j < 8; ++j) G[cb * SG + hg * 8 + j] = hlast[j];
    __syncthreads();
    {
        const int ob = tid >> 3;
        const int oo = tid & 7;
        float s = b_fc[oo];
        const float* hr = &G[ob * SG];
#pragma unroll 8
        for (int h2 = 0; h2 < 64; ++h2)
            s += W_fc[oo * 64 + h2] * hr[h2];
        out[(size_t)(b0 + ob) * 8 + oo] = s;
    }
}

extern "C" void kernel_launch(void* const* d_in, const int* in_sizes, int n_in,
                              void* d_out, int out_size)
{
    const float* x    = (const float*)d_in[0];
    const float* W_ih = (const float*)d_in[1];
    const float* W_hh = (const float*)d_in[2];
    const float* b_ih = (const float*)d_in[3];
    const float* b_hh = (const float*)d_in[4];
    const float* W_fc = (const float*)d_in[5];
    const float* b_fc = (const float*)d_in[6];
    float* out = (float*)d_out;

    size_t smem = (size_t)SMEM_FLTS * sizeof(float);
    cudaFuncSetAttribute(lstm_kernel, cudaFuncAttributeMaxDynamicSharedMemorySize, (int)smem);
    lstm_kernel<<<BATCH / TB, NT, smem>>>(x, W_ih, W_hh, b_ih, b_hh, W_fc, b_fc, out);
}

// round 6
// speedup vs baseline: 3.4453x; 1.1659x over previous
#include <cuda_runtime.h>
#include <cstdint>

#define NT       512
#define TB       64
#define BATCH    8192
#define T_STEPS  128
#define SG       260            // G row stride (floats)

// blocked SMEM layouts (float indices):
//  A: [6 sb][256 rows][16]  = 24576 floats
//  B: [6 sb][64 rows][16]   = 6144 floats
#define A_OFF    0
#define B0_OFF   24576
#define B_FLTS   6144
#define B1_OFF   (B0_OFF + B_FLTS)
#define G_OFF    (B1_OFF + B_FLTS)          // 36864
#define G_FLTS   (64 * SG)                  // 16640
#define SMEM_FLTS (G_OFF + G_FLTS)          // 53504 floats = 214016 B

static __device__ __forceinline__ float rtf32(float v) {
    unsigned u;
    asm("cvt.rna.tf32.f32 %0, %1;" : "=r"(u) : "f"(v));
    return __uint_as_float(u);
}
static __device__ __forceinline__ float tanh_a(float x) {
    float y;
    asm("tanh.approx.f32 %0, %1;" : "=f"(y) : "f"(x));
    return y;
}
static __device__ __forceinline__ void mma_tf32(
    float& d0, float& d1, float& d2, float& d3,
    unsigned a0, unsigned a1, unsigned a2, unsigned a3,
    unsigned b0, unsigned b1)
{
    asm volatile(
        "mma.sync.aligned.m16n8k8.row.col.f32.tf32.tf32.f32 "
        "{%0,%1,%2,%3}, {%4,%5,%6,%7}, {%8,%9}, {%0,%1,%2,%3};"
        : "+f"(d0), "+f"(d1), "+f"(d2), "+f"(d3)
        : "r"(a0), "r"(a1), "r"(a2), "r"(a3), "r"(b0), "r"(b1));
}
static __device__ __forceinline__ unsigned fb(float v) { return __float_as_uint(v); }

// position of k (mod 16) inside a 16-wide superblock:
// thread tq's LDS.128 at 4*tq covers k = {tq, tq+4, tq+8, tq+12}
static __device__ __forceinline__ int pos16(int k) {
    return ((k & 3) << 2) + ((k >> 2) & 3);
}

__global__ __launch_bounds__(NT, 1)
void lstm_kernel(const float* __restrict__ x,
                 const float* __restrict__ W_ih, const float* __restrict__ W_hh,
                 const float* __restrict__ b_ih, const float* __restrict__ b_hh,
                 const float* __restrict__ W_fc, const float* __restrict__ b_fc,
                 float* __restrict__ out)
{
    extern __shared__ float sm[];
    float* A  = sm + A_OFF;
    float* B0 = sm + B0_OFF;
    float* B1 = sm + B1_OFF;
    float* G  = sm + G_OFF;

    const int tid  = threadIdx.x;
    const int lane = tid & 31;
    const int w    = tid >> 5;            // 16 warps
    const int wm   = w & 7;               // M-tile (32 gate rows)
    const int wn   = w >> 3;              // N-tile (32 batches)
    const int g    = lane >> 2;           // 0..7
    const int tq   = lane & 3;            // 0..3
    const int b0   = blockIdx.x * TB;
    const int q    = wm >> 1;             // gate type (0=i,1=f,2=g,3=o)

    // ---- one-time: A fill (gate-major rows, blocked+permuted, tf32) ----
    for (int idx = tid; idx < 256 * 96; idx += NT) {
        int r = idx / 96, k = idx - r * 96;
        float v = (k < 32) ? W_ih[r * 32 + k] : W_hh[r * 64 + (k - 32)];
        A[(k >> 4) * 4096 + r * 16 + pos16(k)] = rtf32(v);
    }
    // zero B0 (h region must be 0 at t=0)
    for (int idx = tid; idx < B_FLTS; idx += NT) B0[idx] = 0.0f;

    // per-warp activation biases (pre-halved for sigmoid gates)
    float bact[4];
#pragma unroll
    for (int i = 0; i < 4; ++i) {
        int grow = wm * 32 + i * 8 + g;
        float bv = b_ih[grow] + b_hh[grow];
        bact[i] = (q == 2) ? bv : 0.5f * bv;
    }

    // combine-thread constants
    const int cb = tid >> 3;              // batch 0..63
    const int hg = tid & 7;               // hidden group (h = 8*hg..+7)
    float c[8];
#pragma unroll
    for (int j = 0; j < 8; ++j) c[j] = 0.0f;
    float hlast[8];

    // h staging positions for k = 32 + 8*hg + j
    int hpos[8];
#pragma unroll
    for (int j = 0; j < 8; ++j) {
        int k = 32 + hg * 8 + j;
        hpos[j] = (k >> 4) * 1024 + cb * 16 + pos16(k);
    }

    // x staging: thread owns (batch cb, k = 4*hg..4*hg+3)
    const float* xrow = x + ((size_t)(b0 + cb) * T_STEPS) * 32 + hg * 4;
    int xpos[4];
#pragma unroll
    for (int j = 0; j < 4; ++j) {
        int k = hg * 4 + j;
        xpos[j] = (k >> 4) * 1024 + cb * 16 + pos16(k);
    }
    {
        float4 xv = *(const float4*)xrow;                     // x_0
        B0[xpos[0]] = rtf32(xv.x);
        B0[xpos[1]] = rtf32(xv.y);
        B0[xpos[2]] = rtf32(xv.z);
        B0[xpos[3]] = rtf32(xv.w);
    }
    float4 xpref = *(const float4*)(xrow + 32);               // x_1
    __syncthreads();

    // GEMM base pointers (conflict-free per 8-lane phase)
    const float* pA = A + (wm * 32 + g) * 16 + 4 * tq;        // + sb*4096 + mt*256 (+128)
    const int    pBoff = (wn * 32 + g) * 16 + 4 * tq;         // + sb*1024 + nt*128

    for (int t = 0; t < T_STEPS; ++t) {
        const float* Bc = (t & 1) ? B1 : B0;
        float*       Bn = (t & 1) ? B0 : B1;
        const float* pB = Bc + pBoff;

        float d[2][4][4];
#pragma unroll
        for (int mt = 0; mt < 2; ++mt)
#pragma unroll
            for (int nt = 0; nt < 4; ++nt)
#pragma unroll
                for (int r = 0; r < 4; ++r) d[mt][nt][r] = 0.0f;

#pragma unroll
        for (int sb = 0; sb < 6; ++sb) {
            float4 aF[2][2], bF[4];
#pragma unroll
            for (int mt = 0; mt < 2; ++mt) {
                aF[mt][0] = *(const float4*)(pA + sb * 4096 + mt * 256);
                aF[mt][1] = *(const float4*)(pA + sb * 4096 + mt * 256 + 128);
            }
#pragma unroll
            for (int nt = 0; nt < 4; ++nt)
                bF[nt] = *(const float4*)(pB + sb * 1024 + nt * 128);
            // kt even: (x,y) components; kt odd: (z,w)
#pragma unroll
            for (int mt = 0; mt < 2; ++mt)
#pragma unroll
                for (int nt = 0; nt < 4; ++nt)
                    mma_tf32(d[mt][nt][0], d[mt][nt][1], d[mt][nt][2], d[mt][nt][3],
                             fb(aF[mt][0].x), fb(aF[mt][1].x),
                             fb(aF[mt][0].y), fb(aF[mt][1].y),
                             fb(bF[nt].x), fb(bF[nt].y));
#pragma unroll
            for (int mt = 0; mt < 2; ++mt)
#pragma unroll
                for (int nt = 0; nt < 4; ++nt)
                    mma_tf32(d[mt][nt][0], d[mt][nt][1], d[mt][nt][2], d[mt][nt][3],
                             fb(aF[mt][0].z), fb(aF[mt][1].z),
                             fb(aF[mt][0].w), fb(aF[mt][1].w),
                             fb(bF[nt].z), fb(bF[nt].w));
        }

        // ---- activation + stage to G[batch][gate-row] (conflict-free stores) ----
#pragma unroll
        for (int mt = 0; mt < 2; ++mt)
#pragma unroll
            for (int s = 0; s < 2; ++s) {
                const int grow = wm * 32 + mt * 16 + s * 8 + g;
                const float bv = bact[mt * 2 + s];
#pragma unroll
                for (int nt = 0; nt < 4; ++nt) {
                    int n0 = wn * 32 + nt * 8 + 2 * tq;
                    float v0 = d[mt][nt][2 * s + 0];
                    float v1 = d[mt][nt][2 * s + 1];
                    float r0, r1;
                    if (q == 2) {
                        r0 = tanh_a(v0 + bv);
                        r1 = tanh_a(v1 + bv);
                    } else {
                        r0 = 0.5f + 0.5f * tanh_a(0.5f * v0 + bv);
                        r1 = 0.5f + 0.5f * tanh_a(0.5f * v1 + bv);
                    }
                    G[n0 * SG + grow]       = r0;
                    G[(n0 + 1) * SG + grow] = r1;
                }
            }
        __syncthreads();

        // ---- combine: c/h update for (cb, h = 8*hg..+7) ----
        {
            const float* gr = &G[cb * SG + hg * 8];
            float4 i0 = ((const float4*)(gr +   0))[0], i1 = ((const float4*)(gr +   0))[1];
            float4 f0 = ((const float4*)(gr +  64))[0], f1 = ((const float4*)(gr +  64))[1];
            float4 g0 = ((const float4*)(gr + 128))[0], g1 = ((const float4*)(gr + 128))[1];
            float4 o0 = ((const float4*)(gr + 192))[0], o1 = ((const float4*)(gr + 192))[1];
            float iv[8] = {i0.x, i0.y, i0.z, i0.w, i1.x, i1.y, i1.z, i1.w};
            float fv[8] = {f0.x, f0.y, f0.z, f0.w, f1.x, f1.y, f1.z, f1.w};
            float gv[8] = {g0.x, g0.y, g0.z, g0.w, g1.x, g1.y, g1.z, g1.w};
            float ov[8] = {o0.x, o0.y, o0.z, o0.w, o1.x, o1.y, o1.z, o1.w};
            float hv[8];
#pragma unroll
            for (int j = 0; j < 8; ++j) {
                float cn = fv[j] * c[j] + iv[j] * gv[j];
                c[j] = cn;
                hv[j] = ov[j] * tanh_a(cn);
            }
            if (t + 1 < T_STEPS) {
#pragma unroll
                for (int j = 0; j < 8; ++j) Bn[hpos[j]] = rtf32(hv[j]);
                Bn[xpos[0]] = rtf32(xpref.x);
                Bn[xpos[1]] = rtf32(xpref.y);
                Bn[xpos[2]] = rtf32(xpref.z);
                Bn[xpos[3]] = rtf32(xpref.w);
                if (t + 2 < T_STEPS)
                    xpref = *(const float4*)(xrow + (size_t)(t + 2) * 32);
            } else {
#pragma unroll
                for (int j = 0; j < 8; ++j) hlast[j] = hv[j];
            }
        }
        __syncthreads();
    }

    // ---- stage h_T into G[batch][0..63], then FC ----
#pragma unroll
    for (int j = 0; j < 8; ++j) G[cb * SG + hg * 8 + j] = hlast[j];
    __syncthreads();
    {
        const int ob = tid >> 3;
        const int oo = tid & 7;
        float s = b_fc[oo];
        const float* hr = &G[ob * SG];
#pragma unroll 8
        for (int h2 = 0; h2 < 64; ++h2)
            s += W_fc[oo * 64 + h2] * hr[h2];
        out[(size_t)(b0 + ob) * 8 + oo] = s;
    }
}

extern "C" void kernel_launch(void* const* d_in, const int* in_sizes, int n_in,
                              void* d_out, int out_size)
{
    const float* x    = (const float*)d_in[0];
    const float* W_ih = (const float*)d_in[1];
    const float* W_hh = (const float*)d_in[2];
    const float* b_ih = (const float*)d_in[3];
    const float* b_hh = (const float*)d_in[4];
    const float* W_fc = (const float*)d_in[5];
    const float* b_fc = (const float*)d_in[6];
    float* out = (float*)d_out;

    size_t smem = (size_t)SMEM_FLTS * sizeof(float);
    cudaFuncSetAttribute(lstm_kernel, cudaFuncAttributeMaxDynamicSharedMemorySize, (int)smem);
    lstm_kernel<<<BATCH / TB, NT, smem>>>(x, W_ih, W_hh, b_ih, b_hh, W_fc, b_fc, out);
}

// round 8
// speedup vs baseline: 4.6913x; 1.3616x over previous
#include <cuda_runtime.h>
#include <cstdint>

#define NT       512
#define TB       64
#define BATCH    8192
#define T_STEPS  128

// blocked SMEM layouts (float indices):
//  A: [6 sb][256 rows][16] = 24576 floats   (rows permuted: p = (h>>3)*32 + q*8 + (h&7))
//  B: [6 sb][64 rows][16]  = 6144 floats
#define A_OFF    0
#define B0_OFF   24576
#define B_FLTS   6144
#define B1_OFF   (B0_OFF + B_FLTS)
#define H_OFF    (B1_OFF + B_FLTS)          // h_T staging [64 batch][68]
#define SH       68
#define SMEM_FLTS (H_OFF + 64 * SH)         // 41216 floats = 164864 B

static __device__ __forceinline__ float rtf32(float v) {
    unsigned u;
    asm("cvt.rna.tf32.f32 %0, %1;" : "=r"(u) : "f"(v));
    return __uint_as_float(u);
}
static __device__ __forceinline__ float tanh_a(float x) {
    float y;
    asm("tanh.approx.f32 %0, %1;" : "=f"(y) : "f"(x));
    return y;
}
static __device__ __forceinline__ void mma_tf32(
    float& d0, float& d1, float& d2, float& d3,
    unsigned a0, unsigned a1, unsigned a2, unsigned a3,
    unsigned b0, unsigned b1)
{
    asm volatile(
        "mma.sync.aligned.m16n8k8.row.col.f32.tf32.tf32.f32 "
        "{%0,%1,%2,%3}, {%4,%5,%6,%7}, {%8,%9}, {%0,%1,%2,%3};"
        : "+f"(d0), "+f"(d1), "+f"(d2), "+f"(d3)
        : "r"(a0), "r"(a1), "r"(a2), "r"(a3), "r"(b0), "r"(b1));
}
static __device__ __forceinline__ unsigned fb(float v) { return __float_as_uint(v); }

// position of k (mod 16) inside a 16-wide superblock:
// thread tq's LDS.128 at 4*tq covers k = {tq, tq+4, tq+8, tq+12}
static __device__ __forceinline__ int pos16(int k) {
    return ((k & 3) << 2) + ((k >> 2) & 3);
}

__global__ __launch_bounds__(NT, 1)
void lstm_kernel(const float* __restrict__ x,
                 const float* __restrict__ W_ih, const float* __restrict__ W_hh,
                 const float* __restrict__ b_ih, const float* __restrict__ b_hh,
                 const float* __restrict__ W_fc, const float* __restrict__ b_fc,
                 float* __restrict__ out)
{
    extern __shared__ float sm[];
    float* A  = sm + A_OFF;
    float* B0 = sm + B0_OFF;
    float* B1 = sm + B1_OFF;
    float* H  = sm + H_OFF;

    const int tid  = threadIdx.x;
    const int lane = tid & 31;
    const int w    = tid >> 5;            // 16 warps
    const int wm   = w & 7;               // M-tile: hidden units wm*8..wm*8+7 (all 4 gates)
    const int wn   = w >> 3;              // N-tile (32 batches)
    const int g    = lane >> 2;           // 0..7
    const int tq   = lane & 3;            // 0..3
    const int b0   = blockIdx.x * TB;

    // ---- one-time: A fill. physical row p -> (q = (p>>3)&3, h = (p>>5)*8 + (p&7)) ----
    for (int idx = tid; idx < 256 * 96; idx += NT) {
        int p = idx / 96, k = idx - p * 96;
        int q = (p >> 3) & 3;
        int h = (p >> 5) * 8 + (p & 7);
        int rl = q * 64 + h;              // logical gate row (PyTorch i,f,g,o order)
        float v = (k < 32) ? W_ih[rl * 32 + k] : W_hh[rl * 64 + (k - 32)];
        A[(k >> 4) * 4096 + p * 16 + pos16(k)] = rtf32(v);
    }
    // zero B0 (h region must be 0 at t=0)
    for (int idx = tid; idx < B_FLTS; idx += NT) B0[idx] = 0.0f;

    // per-thread biases for hidden unit h_own (sigmoid biases pre-halved)
    const int h_own = wm * 8 + g;
    const float bi = 0.5f * (b_ih[0 * 64 + h_own] + b_hh[0 * 64 + h_own]);
    const float bf = 0.5f * (b_ih[1 * 64 + h_own] + b_hh[1 * 64 + h_own]);
    const float bg =         b_ih[2 * 64 + h_own] + b_hh[2 * 64 + h_own];
    const float bo = 0.5f * (b_ih[3 * 64 + h_own] + b_hh[3 * 64 + h_own]);

    // h write base: k-col = 32 + h_own, batch col = wn*32 + nt*8 + 2tq + bl
    const int kcol = 32 + h_own;
    const int hbase = (kcol >> 4) * 1024 + (wn * 32 + 2 * tq) * 16 + pos16(kcol);

    float c[8];
#pragma unroll
    for (int j = 0; j < 8; ++j) c[j] = 0.0f;
    float hlast[8];

    // x staging: thread owns (batch cb, k = 4*hg..4*hg+3)
    const int cb = tid >> 3;
    const int hg = tid & 7;
    const float* xrow = x + ((size_t)(b0 + cb) * T_STEPS) * 32 + hg * 4;
    int xpos[4];
#pragma unroll
    for (int j = 0; j < 4; ++j) {
        int k = hg * 4 + j;
        xpos[j] = (k >> 4) * 1024 + cb * 16 + pos16(k);
    }
    {
        float4 xv = *(const float4*)xrow;                     // x_0
        B0[xpos[0]] = rtf32(xv.x);
        B0[xpos[1]] = rtf32(xv.y);
        B0[xpos[2]] = rtf32(xv.z);
        B0[xpos[3]] = rtf32(xv.w);
    }
    float4 xpref = *(const float4*)(xrow + 32);               // x_1
    __syncthreads();

    // GEMM base pointers (conflict-free per 8-lane phase)
    const float* pA = A + (wm * 32 + g) * 16 + 4 * tq;        // + sb*4096 + mt*256 (+128)
    const int    pBoff = (wn * 32 + g) * 16 + 4 * tq;         // + sb*1024 + nt*128

    for (int t = 0; t < T_STEPS; ++t) {
        const float* Bc = (t & 1) ? B1 : B0;
        float*       Bn = (t & 1) ? B0 : B1;
        const float* pB = Bc + pBoff;

        // d[0][nt][0..1] = i@(b0,b1); d[0][nt][2..3] = f; d[1][nt][0..1] = g; d[1][nt][2..3] = o
        float d[2][4][4];
#pragma unroll
        for (int mt = 0; mt < 2; ++mt)
#pragma unroll
            for (int nt = 0; nt < 4; ++nt)
#pragma unroll
                for (int r = 0; r < 4; ++r) d[mt][nt][r] = 0.0f;

#pragma unroll
        for (int sb = 0; sb < 6; ++sb) {
            float4 aF[2][2], bF[4];
#pragma unroll
            for (int mt = 0; mt < 2; ++mt) {
                aF[mt][0] = *(const float4*)(pA + sb * 4096 + mt * 256);
                aF[mt][1] = *(const float4*)(pA + sb * 4096 + mt * 256 + 128);
            }
#pragma unroll
            for (int nt = 0; nt < 4; ++nt)
                bF[nt] = *(const float4*)(pB + sb * 1024 + nt * 128);
#pragma unroll
            for (int mt = 0; mt < 2; ++mt)
#pragma unroll
                for (int nt = 0; nt < 4; ++nt)
                    mma_tf32(d[mt][nt][0], d[mt][nt][1], d[mt][nt][2], d[mt][nt][3],
                             fb(aF[mt][0].x), fb(aF[mt][1].x),
                             fb(aF[mt][0].y), fb(aF[mt][1].y),
                             fb(bF[nt].x), fb(bF[nt].y));
#pragma unroll
            for (int mt = 0; mt < 2; ++mt)
#pragma unroll
                for (int nt = 0; nt < 4; ++nt)
                    mma_tf32(d[mt][nt][0], d[mt][nt][1], d[mt][nt][2], d[mt][nt][3],
                             fb(aF[mt][0].z), fb(aF[mt][1].z),
                             fb(aF[mt][0].w), fb(aF[mt][1].w),
                             fb(bF[nt].z), fb(bF[nt].w));
        }

        // ---- register-resident LSTM cell update: 4 gates x 8 batches of h_own ----
        const bool last = (t + 1 == T_STEPS);
#pragma unroll
        for (int nt = 0; nt < 4; ++nt) {
#pragma unroll
            for (int bl = 0; bl < 2; ++bl) {
                int j = nt * 2 + bl;
                float iv = 0.5f + 0.5f * tanh_a(0.5f * d[0][nt][bl]     + bi);
                float fv = 0.5f + 0.5f * tanh_a(0.5f * d[0][nt][2 + bl] + bf);
                float gv =               tanh_a(       d[1][nt][bl]     + bg);
                float ov = 0.5f + 0.5f * tanh_a(0.5f * d[1][nt][2 + bl] + bo);
                float cn = fv * c[j] + iv * gv;
                c[j] = cn;
                float hv = ov * tanh_a(cn);
                if (!last) Bn[hbase + nt * 128 + bl * 16] = rtf32(hv);
                else       hlast[j] = hv;
            }
        }

        if (!last) {
            // stage x_{t+1}
            Bn[xpos[0]] = rtf32(xpref.x);
            Bn[xpos[1]] = rtf32(xpref.y);
            Bn[xpos[2]] = rtf32(xpref.z);
            Bn[xpos[3]] = rtf32(xpref.w);
            if (t + 2 < T_STEPS)
                xpref = *(const float4*)(xrow + (size_t)(t + 2) * 32);
        }
        __syncthreads();                  // single barrier per step
    }

    // ---- stage h_T into H[batch][h], then FC ----
#pragma unroll
    for (int nt = 0; nt < 4; ++nt)
#pragma unroll
        for (int bl = 0; bl < 2; ++bl) {
            int col = wn * 32 + nt * 8 + 2 * tq + bl;
            H[col * SH + h_own] = hlast[nt * 2 + bl];
        }
    __syncthreads();
    {
        const int ob = tid >> 3;
        const int oo = tid & 7;
        float s = b_fc[oo];
        const float* hr = &H[ob * SH];
#pragma unroll 8
        for (int h2 = 0; h2 < 64; ++h2)
            s += W_fc[oo * 64 + h2] * hr[h2];
        out[(size_t)(b0 + ob) * 8 + oo] = s;
    }
}

extern "C" void kernel_launch(void* const* d_in, const int* in_sizes, int n_in,
                              void* d_out, int out_size)
{
    const float* x    = (const float*)d_in[0];
    const float* W_ih = (const float*)d_in[1];
    const float* W_hh = (const float*)d_in[2];
    const float* b_ih = (const float*)d_in[3];
    const float* b_hh = (const float*)d_in[4];
    const float* W_fc = (const float*)d_in[5];
    const float* b_fc = (const float*)d_in[6];
    float* out = (float*)d_out;

    size_t smem = (size_t)SMEM_FLTS * sizeof(float);
    cudaFuncSetAttribute(lstm_kernel, cudaFuncAttributeMaxDynamicSharedMemorySize, (int)smem);
    lstm_kernel<<<BATCH / TB, NT, smem>>>(x, W_ih, W_hh, b_ih, b_hh, W_fc, b_fc, out);
}

// round 9
// speedup vs baseline: 8.1753x; 1.7427x over previous
#include <cuda_runtime.h>
#include <cuda_fp16.h>
#include <cstdint>

#define NT       512
#define TB       64
#define BATCH    8192
#define T_STEPS  128

// SMEM byte layout
//  A  : 6kb x 8wm x 2mt x 8g x 4tq units of 16B (8 halves = full A fragment) = 49152 B
//  B0 : 6kb x 64n x 4tq units of 8B (4 halves = full B fragment)             = 12288 B
//  B1 : same                                                                  = 12288 B
//  H  : 64 x 68 floats (FC staging)                                           = 17408 B
#define A_BYTES   49152
#define B_BYTES   12288
#define B0_OFF    A_BYTES
#define B1_OFF    (B0_OFF + B_BYTES)
#define H_OFF     (B1_OFF + B_BYTES)
#define SH        68
#define SMEM_BYTES (H_OFF + 64 * SH * 4)

static __device__ __forceinline__ float tanh_a(float x) {
    float y;
    asm("tanh.approx.f32 %0, %1;" : "=f"(y) : "f"(x));
    return y;
}
static __device__ __forceinline__ void mma_f16(
    float& d0, float& d1, float& d2, float& d3,
    unsigned a0, unsigned a1, unsigned a2, unsigned a3,
    unsigned b0, unsigned b1)
{
    asm volatile(
        "mma.sync.aligned.m16n8k16.row.col.f32.f16.f16.f32 "
        "{%0,%1,%2,%3}, {%4,%5,%6,%7}, {%8,%9}, {%0,%1,%2,%3};"
        : "+f"(d0), "+f"(d1), "+f"(d2), "+f"(d3)
        : "r"(a0), "r"(a1), "r"(a2), "r"(a3), "r"(b0), "r"(b1));
}

// B staging coordinates for feature index k (0..95):
//  kb = k>>4; within 16: km<8 -> (tqp=km>>1, u=km&1), else (tqp=(km-8)>>1, u=2+(km&1))
//  B half-byte = (kb*64 + n)*32 + tqp*8 + u*2
static __device__ __forceinline__ void bcoord(int k, int& kb, int& tqp, int& u) {
    kb = k >> 4;
    int km = k & 15;
    if (km < 8) { tqp = km >> 1;       u = km & 1; }
    else        { tqp = (km - 8) >> 1; u = 2 + (km & 1); }
}

__global__ __launch_bounds__(NT, 1)
void lstm_kernel(const float* __restrict__ x,
                 const float* __restrict__ W_ih, const float* __restrict__ W_hh,
                 const float* __restrict__ b_ih, const float* __restrict__ b_hh,
                 const float* __restrict__ W_fc, const float* __restrict__ b_fc,
                 float* __restrict__ out)
{
    extern __shared__ char smc[];
    char*  Abuf = smc;
    char*  B0   = smc + B0_OFF;
    char*  B1   = smc + B1_OFF;
    float* H    = (float*)(smc + H_OFF);

    const int tid  = threadIdx.x;
    const int lane = tid & 31;
    const int w    = tid >> 5;            // 16 warps
    const int wm   = w & 7;               // M-tile: hidden units wm*8..wm*8+7 (all 4 gates)
    const int wn   = w >> 3;              // N-tile (32 batches)
    const int g    = lane >> 2;           // 0..7
    const int tq   = lane & 3;            // 0..3
    const int b0   = blockIdx.x * TB;

    // ---- one-time A fill (fp16, fragment-native layout) ----
    // logical: physical row p -> (wm=p>>5, mt=(p>>4)&1, s=(p>>3)&1, g=p&7); gate q=mt*2+s; h=wm*8+(p&7)
    for (int idx = tid; idx < 256 * 96; idx += NT) {
        int p = idx / 96, k = idx - p * 96;
        int pwm = p >> 5, mt = (p >> 4) & 1, s = (p >> 3) & 1, pg = p & 7;
        int q = mt * 2 + s;
        int h = pwm * 8 + pg;
        int rl = q * 64 + h;
        float v = (k < 32) ? W_ih[rl * 32 + k] : W_hh[rl * 64 + (k - 32)];
        int kb, tqp, u;
        bcoord(k, kb, tqp, u);            // u: 0,1 -> k8-lo pair; 2,3 -> k8-hi pair
        int hh = u >> 1, b = u & 1;
        // unit = (((kb*8+wm)*2+mt)*8+g)*4+tqp ; half = unit*8 + hh*4 + s*2 + b
        int half_idx = (((((kb * 8 + pwm) * 2 + mt) * 8 + pg) * 4 + tqp) << 3)
                     + hh * 4 + s * 2 + b;
        *(__half*)(Abuf + half_idx * 2) = __float2half_rn(v);
    }
    // zero B0 (h region must be 0 at t=0)
    for (int idx = tid; idx < B_BYTES / 4; idx += NT) ((unsigned*)B0)[idx] = 0u;

    // per-thread biases for hidden unit h_own (sigmoid biases pre-halved)
    const int h_own = wm * 8 + g;
    const float bi = 0.5f * (b_ih[0 * 64 + h_own] + b_hh[0 * 64 + h_own]);
    const float bf = 0.5f * (b_ih[1 * 64 + h_own] + b_hh[1 * 64 + h_own]);
    const float bg =         b_ih[2 * 64 + h_own] + b_hh[2 * 64 + h_own];
    const float bo = 0.5f * (b_ih[3 * 64 + h_own] + b_hh[3 * 64 + h_own]);

    // h write base (feature col 32+h_own; batch n = wn*32 + nt*8 + 2tq + bl)
    int hkb, htqp, hu;
    bcoord(32 + h_own, hkb, htqp, hu);
    const int hbase = hkb * 2048 + (wn * 32 + 2 * tq) * 32 + htqp * 8 + hu * 2;

    float c[8];
#pragma unroll
    for (int j = 0; j < 8; ++j) c[j] = 0.0f;
    float hlast[8];

    // x staging: thread owns (batch cb, k = 4*hg..4*hg+3) -> two half2 stores
    const int cb = tid >> 3;
    const int hg = tid & 7;
    const float* xrow = x + ((size_t)(b0 + cb) * T_STEPS) * 32 + hg * 4;
    int xb0, xb1;                          // byte offsets of the two half2 units
    {
        int kb, tqp, u;
        bcoord(hg * 4 + 0, kb, tqp, u);    // u is 0 or 2
        xb0 = (kb * 64 + cb) * 32 + tqp * 8 + u * 2;
        bcoord(hg * 4 + 2, kb, tqp, u);
        xb1 = (kb * 64 + cb) * 32 + tqp * 8 + u * 2;
    }
    {
        float4 xv = *(const float4*)xrow;                     // x_0
        *(__half2*)(B0 + xb0) = __floats2half2_rn(xv.x, xv.y);
        *(__half2*)(B0 + xb1) = __floats2half2_rn(xv.z, xv.w);
    }
    float4 xpref = *(const float4*)(xrow + 32);               // x_1
    __syncthreads();

    // GEMM base addresses (conflict-free: lanes span contiguous 512B / 256B)
    // A: kb*8192 + wm*1024 + mt*512 + g*64 + tq*16
    const char* pA = Abuf + wm * 1024 + g * 64 + tq * 16;
    // B: kb*2048 + wn*1024 + nt*256 + g*32 + tq*8
    const int pBoff = wn * 1024 + g * 32 + tq * 8;

    for (int t = 0; t < T_STEPS; ++t) {
        const char* Bc = (t & 1) ? B1 : B0;
        char*       Bn = (t & 1) ? B0 : B1;
        const char* pB = Bc + pBoff;

        // d[mt][nt][0..1]: gate 2mt, batches 2tq,2tq+1 ; d[mt][nt][2..3]: gate 2mt+1
        float d[2][4][4];
#pragma unroll
        for (int mt = 0; mt < 2; ++mt)
#pragma unroll
            for (int nt = 0; nt < 4; ++nt)
#pragma unroll
                for (int r = 0; r < 4; ++r) d[mt][nt][r] = 0.0f;

#pragma unroll
        for (int kb = 0; kb < 6; ++kb) {
            uint4 aU[2];
            uint2 bU[4];
#pragma unroll
            for (int mt = 0; mt < 2; ++mt)
                aU[mt] = *(const uint4*)(pA + kb * 8192 + mt * 512);
#pragma unroll
            for (int nt = 0; nt < 4; ++nt)
                bU[nt] = *(const uint2*)(pB + kb * 2048 + nt * 256);
#pragma unroll
            for (int mt = 0; mt < 2; ++mt)
#pragma unroll
                for (int nt = 0; nt < 4; ++nt)
                    mma_f16(d[mt][nt][0], d[mt][nt][1], d[mt][nt][2], d[mt][nt][3],
                            aU[mt].x, aU[mt].y, aU[mt].z, aU[mt].w,
                            bU[nt].x, bU[nt].y);
        }

        // ---- register-resident LSTM cell update ----
        const bool last = (t + 1 == T_STEPS);
#pragma unroll
        for (int nt = 0; nt < 4; ++nt) {
#pragma unroll
            for (int bl = 0; bl < 2; ++bl) {
                int j = nt * 2 + bl;
                float iv = 0.5f + 0.5f * tanh_a(0.5f * d[0][nt][bl]     + bi);
                float fv = 0.5f + 0.5f * tanh_a(0.5f * d[0][nt][2 + bl] + bf);
                float gv =               tanh_a(       d[1][nt][bl]     + bg);
                float ov = 0.5f + 0.5f * tanh_a(0.5f * d[1][nt][2 + bl] + bo);
                float cn = fv * c[j] + iv * gv;
                c[j] = cn;
                float hv = ov * tanh_a(cn);
                if (!last) *(__half*)(Bn + hbase + nt * 256 + bl * 32) = __float2half_rn(hv);
                else       hlast[j] = hv;
            }
        }

        if (!last) {
            // stage x_{t+1}
            *(__half2*)(Bn + xb0) = __floats2half2_rn(xpref.x, xpref.y);
            *(__half2*)(Bn + xb1) = __floats2half2_rn(xpref.z, xpref.w);
            if (t + 2 < T_STEPS)
                xpref = *(const float4*)(xrow + (size_t)(t + 2) * 32);
        }
        __syncthreads();                  // single barrier per step
    }

    // ---- stage h_T into H[batch][h], then FC ----
#pragma unroll
    for (int nt = 0; nt < 4; ++nt)
#pragma unroll
        for (int bl = 0; bl < 2; ++bl) {
            int col = wn * 32 + nt * 8 + 2 * tq + bl;
            H[col * SH + h_own] = hlast[nt * 2 + bl];
        }
    __syncthreads();
    {
        const int ob = tid >> 3;
        const int oo = tid & 7;
        float s = b_fc[oo];
        const float* hr = &H[ob * SH];
#pragma unroll 8
        for (int h2 = 0; h2 < 64; ++h2)
            s += W_fc[oo * 64 + h2] * hr[h2];
        out[(size_t)(b0 + ob) * 8 + oo] = s;
    }
}

extern "C" void kernel_launch(void* const* d_in, const int* in_sizes, int n_in,
                              void* d_out, int out_size)
{
    const float* x    = (const float*)d_in[0];
    const float* W_ih = (const float*)d_in[1];
    const float* W_hh = (const float*)d_in[2];
    const float* b_ih = (const float*)d_in[3];
    const float* b_hh = (const float*)d_in[4];
    const float* W_fc = (const float*)d_in[5];
    const float* b_fc = (const float*)d_in[6];
    float* out = (float*)d_out;

    cudaFuncSetAttribute(lstm_kernel, cudaFuncAttributeMaxDynamicSharedMemorySize, SMEM_BYTES);
    lstm_kernel<<<BATCH / TB, NT, SMEM_BYTES>>>(x, W_ih, W_hh, b_ih, b_hh, W_fc, b_fc, out);
}

// round 10
// speedup vs baseline: 8.5635x; 1.0475x over previous
#include <cuda_runtime.h>
#include <cuda_fp16.h>
#include <cstdint>

#define NT       512
#define TB       64
#define BATCH    8192
#define T_STEPS  128

// SMEM byte layout
//  A  : 6kb x 8wm x 2mt x 8g x 4tq units of 16B (8 halves = full A fragment) = 49152 B
//  B  : 2 groups x 2 phases x (6kb x 32n x 32B)                              = 24576 B
//  H  : 64 x 68 floats (FC staging)                                          = 17408 B
#define A_BYTES   49152
#define BG_BYTES  6144                    // one B buffer (32 batches)
#define B_OFF     A_BYTES
#define H_OFF     (B_OFF + 4 * BG_BYTES)
#define SH        68
#define SMEM_BYTES (H_OFF + 64 * SH * 4)

static __device__ __forceinline__ float tanh_a(float x) {
    float y;
    asm("tanh.approx.f32 %0, %1;" : "=f"(y) : "f"(x));
    return y;
}
static __device__ __forceinline__ void mma_f16(
    float& d0, float& d1, float& d2, float& d3,
    unsigned a0, unsigned a1, unsigned a2, unsigned a3,
    unsigned b0, unsigned b1)
{
    asm volatile(
        "mma.sync.aligned.m16n8k16.row.col.f32.f16.f16.f32 "
        "{%0,%1,%2,%3}, {%4,%5,%6,%7}, {%8,%9}, {%0,%1,%2,%3};"
        : "+f"(d0), "+f"(d1), "+f"(d2), "+f"(d3)
        : "r"(a0), "r"(a1), "r"(a2), "r"(a3), "r"(b0), "r"(b1));
}

// B staging coordinates for feature index k (0..95):
//  kb = k>>4; within 16: km<8 -> (tqp=km>>1, u=km&1), else (tqp=(km-8)>>1, u=2+(km&1))
//  B half-byte (group-local batch n) = kb*1024 + n*32 + tqp*8 + u*2
static __device__ __forceinline__ void bcoord(int k, int& kb, int& tqp, int& u) {
    kb = k >> 4;
    int km = k & 15;
    if (km < 8) { tqp = km >> 1;       u = km & 1; }
    else        { tqp = (km - 8) >> 1; u = 2 + (km & 1); }
}

__global__ __launch_bounds__(NT, 1)
void lstm_kernel(const float* __restrict__ x,
                 const float* __restrict__ W_ih, const float* __restrict__ W_hh,
                 const float* __restrict__ b_ih, const float* __restrict__ b_hh,
                 const float* __restrict__ W_fc, const float* __restrict__ b_fc,
                 float* __restrict__ out)
{
    extern __shared__ char smc[];
    char*  Abuf = smc;
    float* H    = (float*)(smc + H_OFF);

    const int tid  = threadIdx.x;
    const int lane = tid & 31;
    const int w    = tid >> 5;            // 16 warps
    const int wm   = w & 7;               // M-tile: hidden units wm*8..wm*8+7 (all 4 gates)
    const int grp  = tid >> 8;            // batch group 0/1 (warps 0-7 / 8-15)
    const int tid8 = tid & 255;           // thread id within group
    const int g    = lane >> 2;           // 0..7
    const int tq   = lane & 3;            // 0..3
    const int b0   = blockIdx.x * TB;

    char* Bg = smc + B_OFF + grp * 2 * BG_BYTES;   // this group's two B buffers

    // ---- one-time A fill (fp16, fragment-native layout) ----
    for (int idx = tid; idx < 256 * 96; idx += NT) {
        int p = idx / 96, k = idx - p * 96;
        int pwm = p >> 5, mt = (p >> 4) & 1, s = (p >> 3) & 1, pg = p & 7;
        int q = mt * 2 + s;
        int h = pwm * 8 + pg;
        int rl = q * 64 + h;
        float v = (k < 32) ? W_ih[rl * 32 + k] : W_hh[rl * 64 + (k - 32)];
        int kb, tqp, u;
        bcoord(k, kb, tqp, u);
        int hh = u >> 1, b = u & 1;
        int half_idx = (((((kb * 8 + pwm) * 2 + mt) * 8 + pg) * 4 + tqp) << 3)
                     + hh * 4 + s * 2 + b;
        *(__half*)(Abuf + half_idx * 2) = __float2half_rn(v);
    }
    // zero this group's phase-0 B buffer (h region must be 0 at t=0)
    for (int idx = tid8; idx < BG_BYTES / 4; idx += 256) ((unsigned*)Bg)[idx] = 0u;

    // per-thread biases for hidden unit h_own (sigmoid biases pre-halved)
    const int h_own = wm * 8 + g;
    const float bi = 0.5f * (b_ih[0 * 64 + h_own] + b_hh[0 * 64 + h_own]);
    const float bf = 0.5f * (b_ih[1 * 64 + h_own] + b_hh[1 * 64 + h_own]);
    const float bg =         b_ih[2 * 64 + h_own] + b_hh[2 * 64 + h_own];
    const float bo = 0.5f * (b_ih[3 * 64 + h_own] + b_hh[3 * 64 + h_own]);

    // h write base (feature col 32+h_own; group-local batch n = nt*8 + 2tq + bl)
    int hkb, htqp, hu;
    bcoord(32 + h_own, hkb, htqp, hu);
    const int hbase = hkb * 1024 + (2 * tq) * 32 + htqp * 8 + hu * 2;

    float c[8];
#pragma unroll
    for (int j = 0; j < 8; ++j) c[j] = 0.0f;
    float hlast[8];

    // x staging: thread owns (group-local batch cb, k = 4*hg..4*hg+3)
    const int cb = tid8 >> 3;             // 0..31
    const int hg = tid8 & 7;
    const float* xrow = x + ((size_t)(b0 + grp * 32 + cb) * T_STEPS) * 32 + hg * 4;
    int xb0, xb1;
    {
        int kb, tqp, u;
        bcoord(hg * 4 + 0, kb, tqp, u);
        xb0 = kb * 1024 + cb * 32 + tqp * 8 + u * 2;
        bcoord(hg * 4 + 2, kb, tqp, u);
        xb1 = kb * 1024 + cb * 32 + tqp * 8 + u * 2;
    }
    {
        float4 xv = *(const float4*)xrow;                     // x_0
        *(__half2*)(Bg + xb0) = __floats2half2_rn(xv.x, xv.y);
        *(__half2*)(Bg + xb1) = __floats2half2_rn(xv.z, xv.w);
    }
    float4 xpref = *(const float4*)(xrow + 32);               // x_1
    __syncthreads();                      // A + both groups' x_0 staged

    // GEMM base addresses
    const char* pA = Abuf + wm * 1024 + g * 64 + tq * 16;     // + kb*8192 + mt*512
    const int   pBoff = g * 32 + tq * 8;                      // + kb*1024 + nt*256

    const unsigned barid = grp + 1;

    for (int t = 0; t < T_STEPS; ++t) {
        const char* Bc = Bg + ((t & 1) ? BG_BYTES : 0);
        char*       Bn = Bg + ((t & 1) ? 0 : BG_BYTES);
        const char* pB = Bc + pBoff;

        // d[mt][nt][0..1]: gate 2mt, batches 2tq,2tq+1 ; d[mt][nt][2..3]: gate 2mt+1
        float d[2][4][4];
#pragma unroll
        for (int mt = 0; mt < 2; ++mt)
#pragma unroll
            for (int nt = 0; nt < 4; ++nt)
#pragma unroll
                for (int r = 0; r < 4; ++r) d[mt][nt][r] = 0.0f;

#pragma unroll
        for (int kb = 0; kb < 6; ++kb) {
            uint4 aU[2];
            uint2 bU[4];
#pragma unroll
            for (int mt = 0; mt < 2; ++mt)
                aU[mt] = *(const uint4*)(pA + kb * 8192 + mt * 512);
#pragma unroll
            for (int nt = 0; nt < 4; ++nt)
                bU[nt] = *(const uint2*)(pB + kb * 1024 + nt * 256);
#pragma unroll
            for (int mt = 0; mt < 2; ++mt)
#pragma unroll
                for (int nt = 0; nt < 4; ++nt)
                    mma_f16(d[mt][nt][0], d[mt][nt][1], d[mt][nt][2], d[mt][nt][3],
                            aU[mt].x, aU[mt].y, aU[mt].z, aU[mt].w,
                            bU[nt].x, bU[nt].y);
        }

        // ---- register-resident LSTM cell update ----
        const bool last = (t + 1 == T_STEPS);
#pragma unroll
        for (int nt = 0; nt < 4; ++nt) {
#pragma unroll
            for (int bl = 0; bl < 2; ++bl) {
                int j = nt * 2 + bl;
                float iv = 0.5f + 0.5f * tanh_a(0.5f * d[0][nt][bl]     + bi);
                float fv = 0.5f + 0.5f * tanh_a(0.5f * d[0][nt][2 + bl] + bf);
                float gv =               tanh_a(       d[1][nt][bl]     + bg);
                float ov = 0.5f + 0.5f * tanh_a(0.5f * d[1][nt][2 + bl] + bo);
                float cn = fv * c[j] + iv * gv;
                c[j] = cn;
                float hv = ov * tanh_a(cn);
                if (!last) *(__half*)(Bn + hbase + nt * 256 + bl * 32) = __float2half_rn(hv);
                else       hlast[j] = hv;
            }
        }

        if (!last) {
            // stage x_{t+1}
            *(__half2*)(Bn + xb0) = __floats2half2_rn(xpref.x, xpref.y);
            *(__half2*)(Bn + xb1) = __floats2half2_rn(xpref.z, xpref.w);
            if (t + 2 < T_STEPS)
                xpref = *(const float4*)(xrow + (size_t)(t + 2) * 32);
        }
        // group-local barrier: the two groups drift and overlap pipes
        asm volatile("bar.sync %0, %1;" :: "r"(barid), "r"(256) : "memory");
    }

    // ---- stage h_T into H[batch][h], then FC (group-local) ----
#pragma unroll
    for (int nt = 0; nt < 4; ++nt)
#pragma unroll
        for (int bl = 0; bl < 2; ++bl) {
            int col = grp * 32 + nt * 8 + 2 * tq + bl;
            H[col * SH + h_own] = hlast[nt * 2 + bl];
        }
    asm volatile("bar.sync %0, %1;" :: "r"(barid), "r"(256) : "memory");
    {
        const int ob = grp * 32 + (tid8 >> 3);
        const int oo = tid8 & 7;
        float s = b_fc[oo];
        const float* hr = &H[ob * SH];
#pragma unroll 8
        for (int h2 = 0; h2 < 64; ++h2)
            s += W_fc[oo * 64 + h2] * hr[h2];
        out[(size_t)(b0 + ob) * 8 + oo] = s;
    }
}

extern "C" void kernel_launch(void* const* d_in, const int* in_sizes, int n_in,
                              void* d_out, int out_size)
{
    const float* x    = (const float*)d_in[0];
    const float* W_ih = (const float*)d_in[1];
    const float* W_hh = (const float*)d_in[2];
    const float* b_ih = (const float*)d_in[3];
    const float* b_hh = (const float*)d_in[4];
    const float* W_fc = (const float*)d_in[5];
    const float* b_fc = (const float*)d_in[6];
    float* out = (float*)d_out;

    cudaFuncSetAttribute(lstm_kernel, cudaFuncAttributeMaxDynamicSharedMemorySize, SMEM_BYTES);
    lstm_kernel<<<BATCH / TB, NT, SMEM_BYTES>>>(x, W_ih, W_hh, b_ih, b_hh, W_fc, b_fc, out);
}

// round 11
// speedup vs baseline: 8.9903x; 1.0498x over previous
#include <cuda_runtime.h>
#include <cuda_fp16.h>
#include <cstdint>

#define NT       512
#define TB       64
#define BATCH    8192
#define T_STEPS  128

// SMEM byte layout
//  A  : 6kb x 8wm x 2mt x 8g x 4tq units of 16B = 49152 B   (kb 0,1 = x ; kb 2..5 = h)
//  Bh : 2 grp x 2 phase x (4 kb2 x 32n x 32B) = 16384 B
//  X  : 2 grp x 3 buf   x (2 kbx x 32n x 32B) = 12288 B
//  H  : 64 x 68 floats (FC staging)           = 17408 B
#define A_BYTES   49152
#define BH_OFF    A_BYTES
#define X_OFF     (BH_OFF + 16384)
#define H_OFF     (X_OFF + 12288)
#define SH        68
#define SMEM_BYTES (H_OFF + 64 * SH * 4)

static __device__ __forceinline__ float tanh_a(float x) {
    float y;
    asm("tanh.approx.f32 %0, %1;" : "=f"(y) : "f"(x));
    return y;
}
static __device__ __forceinline__ void mma_f16(
    float& d0, float& d1, float& d2, float& d3,
    unsigned a0, unsigned a1, unsigned a2, unsigned a3,
    unsigned b0, unsigned b1)
{
    asm volatile(
        "mma.sync.aligned.m16n8k16.row.col.f32.f16.f16.f32 "
        "{%0,%1,%2,%3}, {%4,%5,%6,%7}, {%8,%9}, {%0,%1,%2,%3};"
        : "+f"(d0), "+f"(d1), "+f"(d2), "+f"(d3)
        : "r"(a0), "r"(a1), "r"(a2), "r"(a3), "r"(b0), "r"(b1));
}

// fragment coordinates for feature index k within a 16-wide block:
//  km<8 -> (tqp=km>>1, u=km&1), else (tqp=(km-8)>>1, u=2+(km&1))
static __device__ __forceinline__ void bcoord(int k, int& kb, int& tqp, int& u) {
    kb = k >> 4;
    int km = k & 15;
    if (km < 8) { tqp = km >> 1;       u = km & 1; }
    else        { tqp = (km - 8) >> 1; u = 2 + (km & 1); }
}

__global__ __launch_bounds__(NT, 1)
void lstm_kernel(const float* __restrict__ x,
                 const float* __restrict__ W_ih, const float* __restrict__ W_hh,
                 const float* __restrict__ b_ih, const float* __restrict__ b_hh,
                 const float* __restrict__ W_fc, const float* __restrict__ b_fc,
                 float* __restrict__ out)
{
    extern __shared__ char smc[];
    char*  Abuf = smc;
    float* H    = (float*)(smc + H_OFF);

    const int tid  = threadIdx.x;
    const int lane = tid & 31;
    const int w    = tid >> 5;            // 16 warps
    const int wm   = w & 7;               // M-tile: hidden units wm*8..wm*8+7 (all 4 gates)
    const int grp  = tid >> 8;            // batch group 0/1
    const int tid8 = tid & 255;
    const int g    = lane >> 2;           // 0..7
    const int tq   = lane & 3;            // 0..3
    const int b0   = blockIdx.x * TB;

    char* BhG = smc + BH_OFF + grp * 8192;   // 2 x 4096B h buffers
    char* XG  = smc + X_OFF  + grp * 6144;   // 3 x 2048B x buffers

    // ---- one-time A fill (fp16, fragment-native layout) ----
    for (int idx = tid; idx < 256 * 96; idx += NT) {
        int p = idx / 96, k = idx - p * 96;
        int pwm = p >> 5, mt = (p >> 4) & 1, s = (p >> 3) & 1, pg = p & 7;
        int q = mt * 2 + s;
        int h = pwm * 8 + pg;
        int rl = q * 64 + h;
        float v = (k < 32) ? W_ih[rl * 32 + k] : W_hh[rl * 64 + (k - 32)];
        int kb, tqp, u;
        bcoord(k, kb, tqp, u);
        int hh = u >> 1, b = u & 1;
        int half_idx = (((((kb * 8 + pwm) * 2 + mt) * 8 + pg) * 4 + tqp) << 3)
                     + hh * 4 + s * 2 + b;
        *(__half*)(Abuf + half_idx * 2) = __float2half_rn(v);
    }
    // zero this group's phase-0 h buffer (h_{-1} = 0)
    for (int idx = tid8; idx < 1024; idx += 256) ((unsigned*)BhG)[idx] = 0u;

    // per-thread biases for hidden unit h_own (sigmoid biases pre-halved)
    const int h_own = wm * 8 + g;
    const float bi = 0.5f * (b_ih[0 * 64 + h_own] + b_hh[0 * 64 + h_own]);
    const float bf = 0.5f * (b_ih[1 * 64 + h_own] + b_hh[1 * 64 + h_own]);
    const float bg =         b_ih[2 * 64 + h_own] + b_hh[2 * 64 + h_own];
    const float bo = 0.5f * (b_ih[3 * 64 + h_own] + b_hh[3 * 64 + h_own]);

    // h write base in Bh: feature h_own -> kb2 = h_own>>4
    int hkb, htqp, hu;
    bcoord(h_own, hkb, htqp, hu);
    const int hbase = hkb * 1024 + (2 * tq) * 32 + htqp * 8 + hu * 2;

    float c[8];
#pragma unroll
    for (int j = 0; j < 8; ++j) c[j] = 0.0f;
    float hlast[8];

    // x staging: thread owns (group-local batch cb, k = 4*hg..4*hg+3)
    const int cb = tid8 >> 3;
    const int hg = tid8 & 7;
    const float* xrow = x + ((size_t)(b0 + grp * 32 + cb) * T_STEPS) * 32 + hg * 4;
    int xo0, xo1;                          // byte offsets within one X buffer
    {
        int kb, tqp, u;
        bcoord(hg * 4 + 0, kb, tqp, u);
        xo0 = kb * 1024 + cb * 32 + tqp * 8 + u * 2;
        bcoord(hg * 4 + 2, kb, tqp, u);
        xo1 = kb * 1024 + cb * 32 + tqp * 8 + u * 2;
    }
    {   // stage x_0 -> X[0], x_1 -> X[1]
        float4 xv = *(const float4*)xrow;
        *(__half2*)(XG + xo0) = __floats2half2_rn(xv.x, xv.y);
        *(__half2*)(XG + xo1) = __floats2half2_rn(xv.z, xv.w);
        xv = *(const float4*)(xrow + 32);
        *(__half2*)(XG + 2048 + xo0) = __floats2half2_rn(xv.x, xv.y);
        *(__half2*)(XG + 2048 + xo1) = __floats2half2_rn(xv.z, xv.w);
    }
    float4 xpref = *(const float4*)(xrow + 64);   // x_2
    __syncthreads();

    // fragment base addresses
    const char* pA = Abuf + wm * 1024 + g * 64 + tq * 16;   // + kb*8192 + mt*512
    const int   fB = g * 32 + tq * 8;                       // + kb*1024 + nt*256

    // d[mt][nt][0..1]: gate 2mt @ batches 2tq,2tq+1 ; [2..3]: gate 2mt+1
    float d[2][4][4];
#pragma unroll
    for (int mt = 0; mt < 2; ++mt)
#pragma unroll
        for (int nt = 0; nt < 4; ++nt)
#pragma unroll
            for (int r = 0; r < 4; ++r) d[mt][nt][r] = 0.0f;

    // prologue: d = Wx . x_0
#pragma unroll
    for (int kb = 0; kb < 2; ++kb) {
        uint4 aU[2];
        uint2 bU[4];
#pragma unroll
        for (int mt = 0; mt < 2; ++mt)
            aU[mt] = *(const uint4*)(pA + kb * 8192 + mt * 512);
#pragma unroll
        for (int nt = 0; nt < 4; ++nt)
            bU[nt] = *(const uint2*)(XG + kb * 1024 + nt * 256 + fB);
#pragma unroll
        for (int mt = 0; mt < 2; ++mt)
#pragma unroll
            for (int nt = 0; nt < 4; ++nt)
                mma_f16(d[mt][nt][0], d[mt][nt][1], d[mt][nt][2], d[mt][nt][3],
                        aU[mt].x, aU[mt].y, aU[mt].z, aU[mt].w,
                        bU[nt].x, bU[nt].y);
    }

    const unsigned barid = grp + 1;

    for (int t = 0; t < T_STEPS; ++t) {
        // ---- MMA_h: accumulate Wh . h_{t-1} (K = 64) ----
        const char* bh = BhG + (t & 1) * 4096;
#pragma unroll
        for (int kb2 = 0; kb2 < 4; ++kb2) {
            uint4 aU[2];
            uint2 bU[4];
#pragma unroll
            for (int mt = 0; mt < 2; ++mt)
                aU[mt] = *(const uint4*)(pA + (2 + kb2) * 8192 + mt * 512);
#pragma unroll
            for (int nt = 0; nt < 4; ++nt)
                bU[nt] = *(const uint2*)(bh + kb2 * 1024 + nt * 256 + fB);
#pragma unroll
            for (int mt = 0; mt < 2; ++mt)
#pragma unroll
                for (int nt = 0; nt < 4; ++nt)
                    mma_f16(d[mt][nt][0], d[mt][nt][1], d[mt][nt][2], d[mt][nt][3],
                            aU[mt].x, aU[mt].y, aU[mt].z, aU[mt].w,
                            bU[nt].x, bU[nt].y);
        }

        // ---- epilogue: gates -> c,h (register-resident, MUFU-heavy) ----
        const bool last = (t + 1 == T_STEPS);
        float hv[8];
#pragma unroll
        for (int nt = 0; nt < 4; ++nt) {
#pragma unroll
            for (int bl = 0; bl < 2; ++bl) {
                int j = nt * 2 + bl;
                float iv = 0.5f + 0.5f * tanh_a(0.5f * d[0][nt][bl]     + bi);
                float fv = 0.5f + 0.5f * tanh_a(0.5f * d[0][nt][2 + bl] + bf);
                float gv =               tanh_a(       d[1][nt][bl]     + bg);
                float ov = 0.5f + 0.5f * tanh_a(0.5f * d[1][nt][2 + bl] + bo);
                float cn = fv * c[j] + iv * gv;
                c[j] = cn;
                hv[j] = ov * tanh_a(cn);
            }
        }

        if (!last) {
            // ---- refill tensor pipe while MUFU chains drain: d = Wx . x_{t+1} ----
#pragma unroll
            for (int mt = 0; mt < 2; ++mt)
#pragma unroll
                for (int nt = 0; nt < 4; ++nt)
#pragma unroll
                    for (int r = 0; r < 4; ++r) d[mt][nt][r] = 0.0f;
            const char* xb = XG + ((t + 1) % 3) * 2048;
#pragma unroll
            for (int kb = 0; kb < 2; ++kb) {
                uint4 aU[2];
                uint2 bU[4];
#pragma unroll
                for (int mt = 0; mt < 2; ++mt)
                    aU[mt] = *(const uint4*)(pA + kb * 8192 + mt * 512);
#pragma unroll
                for (int nt = 0; nt < 4; ++nt)
                    bU[nt] = *(const uint2*)(xb + kb * 1024 + nt * 256 + fB);
#pragma unroll
                for (int mt = 0; mt < 2; ++mt)
#pragma unroll
                    for (int nt = 0; nt < 4; ++nt)
                        mma_f16(d[mt][nt][0], d[mt][nt][1], d[mt][nt][2], d[mt][nt][3],
                                aU[mt].x, aU[mt].y, aU[mt].z, aU[mt].w,
                                bU[nt].x, bU[nt].y);
            }

            // ---- stage h_t -> Bh[next] ----
            char* bn = BhG + ((t + 1) & 1) * 4096;
#pragma unroll
            for (int nt = 0; nt < 4; ++nt)
#pragma unroll
                for (int bl = 0; bl < 2; ++bl)
                    *(__half*)(bn + hbase + nt * 256 + bl * 32) =
                        __float2half_rn(hv[nt * 2 + bl]);

            // ---- stage x_{t+2}, prefetch x_{t+3} ----
            if (t + 2 < T_STEPS) {
                char* xn = XG + ((t + 2) % 3) * 2048;
                *(__half2*)(xn + xo0) = __floats2half2_rn(xpref.x, xpref.y);
                *(__half2*)(xn + xo1) = __floats2half2_rn(xpref.z, xpref.w);
                if (t + 3 < T_STEPS)
                    xpref = *(const float4*)(xrow + (size_t)(t + 3) * 32);
            }
        } else {
#pragma unroll
            for (int j = 0; j < 8; ++j) hlast[j] = hv[j];
        }
        // group-local barrier
        asm volatile("bar.sync %0, %1;" :: "r"(barid), "r"(256) : "memory");
    }

    // ---- stage h_T into H[batch][h], then FC (group-local) ----
#pragma unroll
    for (int nt = 0; nt < 4; ++nt)
#pragma unroll
        for (int bl = 0; bl < 2; ++bl) {
            int col = grp * 32 + nt * 8 + 2 * tq + bl;
            H[col * SH + h_own] = hlast[nt * 2 + bl];
        }
    asm volatile("bar.sync %0, %1;" :: "r"(barid), "r"(256) : "memory");
    {
        const int ob = grp * 32 + (tid8 >> 3);
        const int oo = tid8 & 7;
        float s = b_fc[oo];
        const float* hr = &H[ob * SH];
#pragma unroll 8
        for (int h2 = 0; h2 < 64; ++h2)
            s += W_fc[oo * 64 + h2] * hr[h2];
        out[(size_t)(b0 + ob) * 8 + oo] = s;
    }
}

extern "C" void kernel_launch(void* const* d_in, const int* in_sizes, int n_in,
                              void* d_out, int out_size)
{
    const float* x    = (const float*)d_in[0];
    const float* W_ih = (const float*)d_in[1];
    const float* W_hh = (const float*)d_in[2];
    const float* b_ih = (const float*)d_in[3];
    const float* b_hh = (const float*)d_in[4];
    const float* W_fc = (const float*)d_in[5];
    const float* b_fc = (const float*)d_in[6];
    float* out = (float*)d_out;

    cudaFuncSetAttribute(lstm_kernel, cudaFuncAttributeMaxDynamicSharedMemorySize, SMEM_BYTES);
    lstm_kernel<<<BATCH / TB, NT, SMEM_BYTES>>>(x, W_ih, W_hh, b_ih, b_hh, W_fc, b_fc, out);
}

// round 13
// speedup vs baseline: 9.1192x; 1.0143x over previous
#include <cuda_runtime.h>
#include <cuda_fp16.h>
#include <cstdint>

#define NT       512
#define TB       64
#define BATCH    8192
#define T_STEPS  128

// SMEM byte layout
//  A  : 6kb x 8wm x 2mt x 8g x 4tq units of 16B = 49152 B   (kb 0,1 = x ; kb 2..5 = h)
//  Bh : 2 grp x 2 phase x (4 kb2 x 32n x 32B) = 16384 B
//  X  : 2 grp x 3 buf   x (2 kbx x 32n x 32B) = 12288 B
//  H  : 64 x 68 floats (FC staging)           = 17408 B
#define A_BYTES   49152
#define BH_OFF    A_BYTES
#define X_OFF     (BH_OFF + 16384)
#define H_OFF     (X_OFF + 12288)
#define SH        68
#define SMEM_BYTES (H_OFF + 64 * SH * 4)

static __device__ __forceinline__ float tanh_a(float x) {
    float y;
    asm("tanh.approx.f32 %0, %1;" : "=f"(y) : "f"(x));
    return y;
}
static __device__ __forceinline__ __half2 tanh2(__half2 x) {
    unsigned r, xi = *(unsigned*)&x;
    asm("tanh.approx.f16x2 %0, %1;" : "=r"(r) : "r"(xi));
    return *(__half2*)&r;
}
static __device__ __forceinline__ void mma_f16(
    float& d0, float& d1, float& d2, float& d3,
    unsigned a0, unsigned a1, unsigned a2, unsigned a3,
    unsigned b0, unsigned b1)
{
    asm volatile(
        "mma.sync.aligned.m16n8k16.row.col.f32.f16.f16.f32 "
        "{%0,%1,%2,%3}, {%4,%5,%6,%7}, {%8,%9}, {%0,%1,%2,%3};"
        : "+f"(d0), "+f"(d1), "+f"(d2), "+f"(d3)
        : "r"(a0), "r"(a1), "r"(a2), "r"(a3), "r"(b0), "r"(b1));
}

// fragment coordinates for feature index k within a 16-wide block
static __device__ __forceinline__ void bcoord(int k, int& kb, int& tqp, int& u) {
    kb = k >> 4;
    int km = k & 15;
    if (km < 8) { tqp = km >> 1;       u = km & 1; }
    else        { tqp = (km - 8) >> 1; u = 2 + (km & 1); }
}

__global__ __launch_bounds__(NT, 1)
void lstm_kernel(const float* __restrict__ x,
                 const float* __restrict__ W_ih, const float* __restrict__ W_hh,
                 const float* __restrict__ b_ih, const float* __restrict__ b_hh,
                 const float* __restrict__ W_fc, const float* __restrict__ b_fc,
                 float* __restrict__ out)
{
    extern __shared__ char smc[];
    char*  Abuf = smc;
    float* H    = (float*)(smc + H_OFF);

    const int tid  = threadIdx.x;
    const int lane = tid & 31;
    const int w    = tid >> 5;            // 16 warps
    const int wm   = w & 7;               // M-tile: hidden units wm*8..wm*8+7 (all 4 gates)
    const int grp  = tid >> 8;            // batch group 0/1
    const int tid8 = tid & 255;
    const int g    = lane >> 2;           // 0..7
    const int tq   = lane & 3;            // 0..3
    const int b0   = blockIdx.x * TB;

    char* BhG = smc + BH_OFF + grp * 8192;   // 2 x 4096B h buffers
    char* XG  = smc + X_OFF  + grp * 6144;   // 3 x 2048B x buffers

    // ---- one-time A fill (fp16, fragment-native layout) ----
    for (int idx = tid; idx < 256 * 96; idx += NT) {
        int p = idx / 96, k = idx - p * 96;
        int pwm = p >> 5, mt = (p >> 4) & 1, s = (p >> 3) & 1, pg = p & 7;
        int q = mt * 2 + s;
        int h = pwm * 8 + pg;
        int rl = q * 64 + h;
        float v = (k < 32) ? W_ih[rl * 32 + k] : W_hh[rl * 64 + (k - 32)];
        int kb, tqp, u;
        bcoord(k, kb, tqp, u);
        int hh = u >> 1, b = u & 1;
        int half_idx = (((((kb * 8 + pwm) * 2 + mt) * 8 + pg) * 4 + tqp) << 3)
                     + hh * 4 + s * 2 + b;
        *(__half*)(Abuf + half_idx * 2) = __float2half_rn(v);
    }
    // zero this group's phase-0 h buffer (h_{-1} = 0)
    for (int idx = tid8; idx < 1024; idx += 256) ((unsigned*)BhG)[idx] = 0u;

    // per-thread biases for hidden unit h_own
    const int h_own = wm * 8 + g;
    const float bi = 0.5f * (b_ih[0 * 64 + h_own] + b_hh[0 * 64 + h_own]);
    const float bf = 0.5f * (b_ih[1 * 64 + h_own] + b_hh[1 * 64 + h_own]);
    const float bg =         b_ih[2 * 64 + h_own] + b_hh[2 * 64 + h_own];
    const float bo = 0.5f * (b_ih[3 * 64 + h_own] + b_hh[3 * 64 + h_own]);
    const __half2 bi2 = __float2half2_rn(bi);
    const __half2 bf2 = __float2half2_rn(bf);
    const __half2 bg2 = __float2half2_rn(bg);
    const __half2 bo2 = __float2half2_rn(bo);
    const __half2 h05 = __float2half2_rn(0.5f);

    // h write base in Bh: feature h_own -> kb2 = h_own>>4
    int hkb, htqp, hu;
    bcoord(h_own, hkb, htqp, hu);
    const int hbase = hkb * 1024 + (2 * tq) * 32 + htqp * 8 + hu * 2;

    float c[8];
#pragma unroll
    for (int j = 0; j < 8; ++j) c[j] = 0.0f;
    float hlast[8];

    // x staging: thread owns (group-local batch cb, k = 4*hg..4*hg+3)
    const int cb = tid8 >> 3;
    const int hg = tid8 & 7;
    const float* xrow = x + ((size_t)(b0 + grp * 32 + cb) * T_STEPS) * 32 + hg * 4;
    int xo0, xo1;
    {
        int kb, tqp, u;
        bcoord(hg * 4 + 0, kb, tqp, u);
        xo0 = kb * 1024 + cb * 32 + tqp * 8 + u * 2;
        bcoord(hg * 4 + 2, kb, tqp, u);
        xo1 = kb * 1024 + cb * 32 + tqp * 8 + u * 2;
    }
    {   // stage x_0 -> X[0], x_1 -> X[1]
        float4 xv = *(const float4*)xrow;
        *(__half2*)(XG + xo0) = __floats2half2_rn(xv.x, xv.y);
        *(__half2*)(XG + xo1) = __floats2half2_rn(xv.z, xv.w);
        xv = *(const float4*)(xrow + 32);
        *(__half2*)(XG + 2048 + xo0) = __floats2half2_rn(xv.x, xv.y);
        *(__half2*)(XG + 2048 + xo1) = __floats2half2_rn(xv.z, xv.w);
    }
    float4 xpref = *(const float4*)(xrow + 64);   // x_2
    __syncthreads();

    // fragment base addresses
    const char* pA = Abuf + wm * 1024 + g * 64 + tq * 16;   // + kb*8192 + mt*512
    const int   fB = g * 32 + tq * 8;                       // + kb*1024 + nt*256

    // d[mt][nt][0..1]: gate 2mt @ batches 2tq,2tq+1 ; [2..3]: gate 2mt+1
    float d[2][4][4];
#pragma unroll
    for (int mt = 0; mt < 2; ++mt)
#pragma unroll
        for (int nt = 0; nt < 4; ++nt)
#pragma unroll
            for (int r = 0; r < 4; ++r) d[mt][nt][r] = 0.0f;

    // prologue: d = Wx . x_0
#pragma unroll
    for (int kb = 0; kb < 2; ++kb) {
        uint4 aU[2];
        uint2 bU[4];
#pragma unroll
        for (int mt = 0; mt < 2; ++mt)
            aU[mt] = *(const uint4*)(pA + kb * 8192 + mt * 512);
#pragma unroll
        for (int nt = 0; nt < 4; ++nt)
            bU[nt] = *(const uint2*)(XG + kb * 1024 + nt * 256 + fB);
#pragma unroll
        for (int mt = 0; mt < 2; ++mt)
#pragma unroll
            for (int nt = 0; nt < 4; ++nt)
                mma_f16(d[mt][nt][0], d[mt][nt][1], d[mt][nt][2], d[mt][nt][3],
                        aU[mt].x, aU[mt].y, aU[mt].z, aU[mt].w,
                        bU[nt].x, bU[nt].y);
    }

    const unsigned barid = grp + 1;

    for (int t = 0; t < T_STEPS; ++t) {
        // ---- MMA_h: accumulate Wh . h_{t-1} (K = 64) ----
        const char* bh = BhG + (t & 1) * 4096;
#pragma unroll
        for (int kb2 = 0; kb2 < 4; ++kb2) {
            uint4 aU[2];
            uint2 bU[4];
#pragma unroll
            for (int mt = 0; mt < 2; ++mt)
                aU[mt] = *(const uint4*)(pA + (2 + kb2) * 8192 + mt * 512);
#pragma unroll
            for (int nt = 0; nt < 4; ++nt)
                bU[nt] = *(const uint2*)(bh + kb2 * 1024 + nt * 256 + fB);
#pragma unroll
            for (int mt = 0; mt < 2; ++mt)
#pragma unroll
                for (int nt = 0; nt < 4; ++nt)
                    mma_f16(d[mt][nt][0], d[mt][nt][1], d[mt][nt][2], d[mt][nt][3],
                            aU[mt].x, aU[mt].y, aU[mt].z, aU[mt].w,
                            bU[nt].x, bU[nt].y);
        }

        const bool last = (t + 1 == T_STEPS);

        if (!last) {
            // ---- packed-half epilogue: 5 tanh2 per nt (20 MUFU/thread) ----
            __half2 hv2[4];
#pragma unroll
            for (int nt = 0; nt < 4; ++nt) {
                __half2 dih = __floats2half2_rn(d[0][nt][0], d[0][nt][1]);
                __half2 dfh = __floats2half2_rn(d[0][nt][2], d[0][nt][3]);
                __half2 dgh = __floats2half2_rn(d[1][nt][0], d[1][nt][1]);
                __half2 doh = __floats2half2_rn(d[1][nt][2], d[1][nt][3]);
                __half2 iv = __hfma2(tanh2(__hfma2(dih, h05, bi2)), h05, h05);
                __half2 fv = __hfma2(tanh2(__hfma2(dfh, h05, bf2)), h05, h05);
                __half2 gv = tanh2(__hadd2(dgh, bg2));
                __half2 ov = __hfma2(tanh2(__hfma2(doh, h05, bo2)), h05, h05);
                __half2 ig = __hmul2(iv, gv);
                float cn0 = __low2float(fv)  * c[2 * nt]     + __low2float(ig);
                float cn1 = __high2float(fv) * c[2 * nt + 1] + __high2float(ig);
                c[2 * nt]     = cn0;
                c[2 * nt + 1] = cn1;
                hv2[nt] = __hmul2(ov, tanh2(__floats2half2_rn(cn0, cn1)));
            }

            // ---- refill tensor pipe while MUFU chains drain: d = Wx . x_{t+1} ----
#pragma unroll
            for (int mt = 0; mt < 2; ++mt)
#pragma unroll
                for (int nt = 0; nt < 4; ++nt)
#pragma unroll
                    for (int r = 0; r < 4; ++r) d[mt][nt][r] = 0.0f;
            const char* xb = XG + ((t + 1) % 3) * 2048;
#pragma unroll
            for (int kb = 0; kb < 2; ++kb) {
                uint4 aU[2];
                uint2 bU[4];
#pragma unroll
                for (int mt = 0; mt < 2; ++mt)
                    aU[mt] = *(const uint4*)(pA + kb * 8192 + mt * 512);
#pragma unroll
                for (int nt = 0; nt < 4; ++nt)
                    bU[nt] = *(const uint2*)(xb + kb * 1024 + nt * 256 + fB);
#pragma unroll
                for (int mt = 0; mt < 2; ++mt)
#pragma unroll
                    for (int nt = 0; nt < 4; ++nt)
                        mma_f16(d[mt][nt][0], d[mt][nt][1], d[mt][nt][2], d[mt][nt][3],
                                aU[mt].x, aU[mt].y, aU[mt].z, aU[mt].w,
                                bU[nt].x, bU[nt].y);
            }

            // ---- stage h_t -> Bh[next] ----
            char* bn = BhG + ((t + 1) & 1) * 4096;
#pragma unroll
            for (int nt = 0; nt < 4; ++nt) {
                *(__half*)(bn + hbase + nt * 256)      = __low2half(hv2[nt]);
                *(__half*)(bn + hbase + nt * 256 + 32) = __high2half(hv2[nt]);
            }

            // ---- stage x_{t+2}, prefetch x_{t+3} ----
            if (t + 2 < T_STEPS) {
                char* xn = XG + ((t + 2) % 3) * 2048;
                *(__half2*)(xn + xo0) = __floats2half2_rn(xpref.x, xpref.y);
                *(__half2*)(xn + xo1) = __floats2half2_rn(xpref.z, xpref.w);
                if (t + 3 < T_STEPS)
                    xpref = *(const float4*)(xrow + (size_t)(t + 3) * 32);
            }
        } else {
            // final step: full fp32 epilogue for h_T precision
#pragma unroll
            for (int nt = 0; nt < 4; ++nt) {
#pragma unroll
                for (int bl = 0; bl < 2; ++bl) {
                    int j = nt * 2 + bl;
                    float iv = 0.5f + 0.5f * tanh_a(0.5f * d[0][nt][bl]     + bi);
                    float fv = 0.5f + 0.5f * tanh_a(0.5f * d[0][nt][2 + bl] + bf);
                    float gv =               tanh_a(       d[1][nt][bl]     + bg);
                    float ov = 0.5f + 0.5f * tanh_a(0.5f * d[1][nt][2 + bl] + bo);
                    float cn = fv * c[j] + iv * gv;
                    c[j] = cn;
                    hlast[j] = ov * tanh_a(cn);
                }
            }
        }
        // group-local barrier
        asm volatile("bar.sync %0, %1;" :: "r"(barid), "r"(256) : "memory");
    }

    // ---- stage h_T into H[batch][h], then FC (group-local) ----
#pragma unroll
    for (int nt = 0; nt < 4; ++nt)
#pragma unroll
        for (int bl = 0; bl < 2; ++bl) {
            int col = grp * 32 + nt * 8 + 2 * tq + bl;
            H[col * SH + h_own] = hlast[nt * 2 + bl];
        }
    asm volatile("bar.sync %0, %1;" :: "r"(barid), "r"(256) : "memory");
    {
        const int ob = grp * 32 + (tid8 >> 3);
        const int oo = tid8 & 7;
        float s = b_fc[oo];
        const float* hr = &H[ob * SH];
#pragma unroll 8
        for (int h2 = 0; h2 < 64; ++h2)
            s += W_fc[oo * 64 + h2] * hr[h2];
        out[(size_t)(b0 + ob) * 8 + oo] = s;
    }
}

extern "C" void kernel_launch(void* const* d_in, const int* in_sizes, int n_in,
                              void* d_out, int out_size)
{
    const float* x    = (const float*)d_in[0];
    const float* W_ih = (const float*)d_in[1];
    const float* W_hh = (const float*)d_in[2];
    const float* b_ih = (const float*)d_in[3];
    const float* b_hh = (const float*)d_in[4];
    const float* W_fc = (const float*)d_in[5];
    const float* b_fc = (const float*)d_in[6];
    float* out = (float*)d_out;

    cudaFuncSetAttribute(lstm_kernel, cudaFuncAttributeMaxDynamicSharedMemorySize, SMEM_BYTES);
    lstm_kernel<<<BATCH / TB, NT, SMEM_BYTES>>>(x, W_ih, W_hh, b_ih, b_hh, W_fc, b_fc, out);
}